// round 4
// baseline (speedup 1.0000x reference)
#include <cuda_runtime.h>
#include <cuda_bf16.h>

// NeRF raw2outputs. R3 (resubmit — prior run hit a host-side
// cudaErrorSystemNotReady infra flake before kernel launch).
// TWO warps per ray (96 samples = 3 chunks each) to halve per-warp register
// state and recover occupancy; cross-warp transmittance carry and final
// reductions via one smem exchange each.
//
// Output layout (tuple flattened in order), N = num rays:
//   [0 , 3N)     rgb_map   [N,3]
//   [3N, 4N)     disp_map  [N,1]
//   [4N, 5N)     acc_map   [N,1]
//   [5N, 197N)   weights   [N,192]
//   [197N, 198N) depth_map [N,1]

#define FULL 0xffffffffu
#define NSAMP 192
#define NCH 3              // chunks per warp
#define INF_DIST 1e10f
#define WARPS_PER_BLK 8    // 4 rays per block

__global__ __launch_bounds__(256)
void nerf_render_kernel(const float4* __restrict__ raw4,
                        const float*  __restrict__ z_vals,
                        const float*  __restrict__ rays_d,
                        float* __restrict__ out,
                        int N)
{
    __shared__ float s_tot[WARPS_PER_BLK];         // per-warp transmittance product
    __shared__ float s_part[WARPS_PER_BLK / 2][5]; // odd-warp partial sums

    const int warp = threadIdx.x >> 5;
    const int lane = threadIdx.x & 31;
    const int pair = warp >> 1;                   // ray slot within block
    const int half = warp & 1;                    // 0: samples 0-95, 1: 96-191

    int ray = blockIdx.x * (WARPS_PER_BLK / 2) + pair;
    if (ray >= N) ray = N - 1;                    // duplicate work, keeps barriers uniform

    const long rbase = (long)ray * NSAMP;
    const long base  = rbase + half * 96;

    // ---- front-batch global loads (6 independent LDGs + boundary z) ----
    float4 rv[NCH];
    float  zv[NCH];
#pragma unroll
    for (int c = 0; c < NCH; ++c)
        rv[c] = raw4[base + c * 32 + lane];
#pragma unroll
    for (int c = 0; c < NCH; ++c)
        zv[c] = z_vals[base + c * 32 + lane];
    // z of the sample after this warp's range (only meaningful for half==0)
    const float zbound = (half == 0) ? z_vals[rbase + 96] : 0.f;

    const float dx = rays_d[3 * ray + 0];
    const float dy = rays_d[3 * ray + 1];
    const float dz = rays_d[3 * ray + 2];
    const float nrm = sqrtf(dx * dx + dy * dy + dz * dz);

    // ---- sigmoid rgb immediately (drop the float4s) ----
    float sr[NCH], sg[NCH], sb[NCH], sig[NCH];
#pragma unroll
    for (int c = 0; c < NCH; ++c) {
        sr[c]  = __fdividef(1.f, 1.f + __expf(-rv[c].x));
        sg[c]  = __fdividef(1.f, 1.f + __expf(-rv[c].y));
        sb[c]  = __fdividef(1.f, 1.f + __expf(-rv[c].z));
        sig[c] = fmaxf(rv[c].w, 0.f);
    }

    // ---- per-sample alpha, t ----
    float alpha[NCH], p[NCH];
#pragma unroll
    for (int c = 0; c < NCH; ++c) {
        const float z  = zv[c];
        const float zn = __shfl_down_sync(FULL, z, 1);
        float dist;
        if (c < NCH - 1) {
            const float zfn = __shfl_sync(FULL, zv[c + 1], 0);
            dist = (lane == 31) ? (zfn - z) : (zn - z);
        } else if (half == 0) {
            dist = (lane == 31) ? (zbound - z) : (zn - z);
        } else {
            dist = (lane == 31) ? INF_DIST : (zn - z);
        }
        dist *= nrm;
        alpha[c] = 1.f - __expf(-sig[c] * dist);
        p[c] = 1.f - alpha[c] + 1e-10f;
    }

    // ---- 3 interleaved inclusive product scans ----
#pragma unroll
    for (int off = 1; off < 32; off <<= 1) {
#pragma unroll
        for (int c = 0; c < NCH; ++c) {
            const float u = __shfl_up_sync(FULL, p[c], off);
            if (lane >= off) p[c] *= u;
        }
    }

    float exc[NCH], tot[NCH];
#pragma unroll
    for (int c = 0; c < NCH; ++c) {
        exc[c] = __shfl_up_sync(FULL, p[c], 1);
        if (lane == 0) exc[c] = 1.f;
        tot[c] = __shfl_sync(FULL, p[c], 31);
    }

    // warp-local carries + warp total -> smem for cross-warp prefix
    const float c1 = tot[0];
    const float c2 = tot[0] * tot[1];
    if (lane == 0) s_tot[warp] = c2 * tot[2];
    __syncthreads();
    const float prefix = (half == 1) ? s_tot[warp - 1] : 1.f;

    const float carry[NCH] = {prefix, prefix * c1, prefix * c2};

    // ---- weights, accumulation, stores ----
    float* __restrict__ wout = out + (long)5 * N;
    float r_sum = 0.f, g_sum = 0.f, b_sum = 0.f, d_sum = 0.f, a_sum = 0.f;

#pragma unroll
    for (int c = 0; c < NCH; ++c) {
        const float w = alpha[c] * carry[c] * exc[c];
        r_sum += w * sr[c];
        g_sum += w * sg[c];
        b_sum += w * sb[c];
        d_sum += w * zv[c];
        a_sum += w;
        wout[base + c * 32 + lane] = w;   // coalesced
    }

    // ---- warp reductions ----
#pragma unroll
    for (int off = 16; off; off >>= 1) {
        r_sum += __shfl_down_sync(FULL, r_sum, off);
        g_sum += __shfl_down_sync(FULL, g_sum, off);
        b_sum += __shfl_down_sync(FULL, b_sum, off);
        d_sum += __shfl_down_sync(FULL, d_sum, off);
        a_sum += __shfl_down_sync(FULL, a_sum, off);
    }

    // odd warp publishes partials; even warp combines and writes maps
    if (half == 1 && lane == 0) {
        s_part[pair][0] = r_sum;
        s_part[pair][1] = g_sum;
        s_part[pair][2] = b_sum;
        s_part[pair][3] = d_sum;
        s_part[pair][4] = a_sum;
    }
    __syncthreads();

    if (half == 0 && lane == 0) {
        r_sum += s_part[pair][0];
        g_sum += s_part[pair][1];
        b_sum += s_part[pair][2];
        d_sum += s_part[pair][3];
        a_sum += s_part[pair][4];

        out[3 * ray + 0] = r_sum;
        out[3 * ray + 1] = g_sum;
        out[3 * ray + 2] = b_sum;

        const float acc = a_sum;
        float depth = d_sum;
        if (acc <= 1e-10f) depth = INF_DIST;
        const float ratio = __fdividef(depth, acc);
        const float disp  = __fdividef(1.f, fmaxf(1e-10f, ratio));

        out[(long)3 * N + ray]   = disp;
        out[(long)4 * N + ray]   = acc;
        out[(long)197 * N + ray] = depth;
    }
}

extern "C" void kernel_launch(void* const* d_in, const int* in_sizes, int n_in,
                              void* d_out, int out_size)
{
    const float4* raw4   = (const float4*)d_in[0];
    const float*  z_vals = (const float*)d_in[1];
    const float*  rays_d = (const float*)d_in[2];
    float* out = (float*)d_out;

    const int N = in_sizes[2] / 3;                // num rays
    const int rays_per_blk = WARPS_PER_BLK / 2;   // 4
    const int blocks = (N + rays_per_blk - 1) / rays_per_blk;
    nerf_render_kernel<<<blocks, WARPS_PER_BLK * 32>>>(raw4, z_vals, rays_d, out, N);
}

// round 5
// speedup vs baseline: 1.2414x; 1.2414x over previous
#include <cuda_runtime.h>
#include <cuda_bf16.h>

// NeRF raw2outputs. R5 = R2 structure (one warp per ray, 6 chunks of 32,
// front-batched loads, ILP'd product scans) + streaming cache hints:
// __ldcs on the read-once raw/z streams, __stcs on the write-once weights.
//
// Output layout (tuple flattened in order), N = num rays:
//   [0 , 3N)     rgb_map   [N,3]
//   [3N, 4N)     disp_map  [N,1]
//   [4N, 5N)     acc_map   [N,1]
//   [5N, 197N)   weights   [N,192]
//   [197N, 198N) depth_map [N,1]

#define FULL 0xffffffffu
#define NSAMP 192
#define NCHUNK 6
#define INF_DIST 1e10f

__global__ __launch_bounds__(256)
void nerf_render_kernel(const float4* __restrict__ raw4,
                        const float*  __restrict__ z_vals,
                        const float*  __restrict__ rays_d,
                        float* __restrict__ out,
                        int N)
{
    const int warp_in_blk = threadIdx.x >> 5;
    const int lane        = threadIdx.x & 31;
    const int ray = blockIdx.x * (blockDim.x >> 5) + warp_in_blk;
    if (ray >= N) return;

    const long base = (long)ray * NSAMP;

    // ---- front-batch ALL global loads (12 independent LDGs in flight) ----
    float4 rv[NCHUNK];
    float  zv[NCHUNK];
#pragma unroll
    for (int c = 0; c < NCHUNK; ++c)
        rv[c] = __ldcs(&raw4[base + c * 32 + lane]);     // read-once: evict-first
#pragma unroll
    for (int c = 0; c < NCHUNK; ++c)
        zv[c] = __ldcs(&z_vals[base + c * 32 + lane]);   // read-once: evict-first

    const float dx = rays_d[3 * ray + 0];
    const float dy = rays_d[3 * ray + 1];
    const float dz = rays_d[3 * ray + 2];
    const float nrm = sqrtf(dx * dx + dy * dy + dz * dz);

    // ---- per-sample alpha and t = 1-alpha+eps (independent across chunks) ----
    float alpha[NCHUNK], p[NCHUNK];
#pragma unroll
    for (int c = 0; c < NCHUNK; ++c) {
        const float z  = zv[c];
        const float zn = __shfl_down_sync(FULL, z, 1);
        float dist;
        if (c < NCHUNK - 1) {
            const float zfn = __shfl_sync(FULL, zv[c + 1], 0);
            dist = (lane == 31) ? (zfn - z) : (zn - z);
        } else {
            dist = (lane == 31) ? INF_DIST : (zn - z);
        }
        dist *= nrm;
        const float sigma = fmaxf(rv[c].w, 0.f);
        alpha[c] = 1.f - __expf(-sigma * dist);
        p[c] = 1.f - alpha[c] + 1e-10f;
    }

    // ---- 6 independent inclusive product scans, interleaved for ILP ----
#pragma unroll
    for (int off = 1; off < 32; off <<= 1) {
#pragma unroll
        for (int c = 0; c < NCHUNK; ++c) {
            const float u = __shfl_up_sync(FULL, p[c], off);
            if (lane >= off) p[c] *= u;
        }
    }

    // exclusive prefix within chunk + chunk totals (independent shuffles)
    float exc[NCHUNK], tot[NCHUNK];
#pragma unroll
    for (int c = 0; c < NCHUNK; ++c) {
        exc[c] = __shfl_up_sync(FULL, p[c], 1);
        if (lane == 0) exc[c] = 1.f;
        tot[c] = __shfl_sync(FULL, p[c], 31);
    }

    // cross-chunk carry prefix (5 scalar multiplies)
    float carry[NCHUNK];
    carry[0] = 1.f;
#pragma unroll
    for (int c = 1; c < NCHUNK; ++c)
        carry[c] = carry[c - 1] * tot[c - 1];

    // ---- weights, color/depth accumulation, streaming stores ----
    float* __restrict__ wout = out + (long)5 * N;
    float r_sum = 0.f, g_sum = 0.f, b_sum = 0.f, d_sum = 0.f, a_sum = 0.f;

#pragma unroll
    for (int c = 0; c < NCHUNK; ++c) {
        const float w = alpha[c] * carry[c] * exc[c];

        const float sr = __fdividef(1.f, 1.f + __expf(-rv[c].x));
        const float sg = __fdividef(1.f, 1.f + __expf(-rv[c].y));
        const float sb = __fdividef(1.f, 1.f + __expf(-rv[c].z));

        r_sum += w * sr;
        g_sum += w * sg;
        b_sum += w * sb;
        d_sum += w * zv[c];
        a_sum += w;

        __stcs(&wout[base + c * 32 + lane], w);   // write-once: evict-first
    }

    // ---- warp reductions ----
#pragma unroll
    for (int off = 16; off; off >>= 1) {
        r_sum += __shfl_down_sync(FULL, r_sum, off);
        g_sum += __shfl_down_sync(FULL, g_sum, off);
        b_sum += __shfl_down_sync(FULL, b_sum, off);
        d_sum += __shfl_down_sync(FULL, d_sum, off);
        a_sum += __shfl_down_sync(FULL, a_sum, off);
    }

    if (lane == 0) {
        out[3 * ray + 0] = r_sum;
        out[3 * ray + 1] = g_sum;
        out[3 * ray + 2] = b_sum;

        const float acc = a_sum;
        float depth = d_sum;
        if (acc <= 1e-10f) depth = INF_DIST;
        const float ratio = __fdividef(depth, acc);
        const float disp  = __fdividef(1.f, fmaxf(1e-10f, ratio));

        out[(long)3 * N + ray]   = disp;
        out[(long)4 * N + ray]   = acc;
        out[(long)197 * N + ray] = depth;
    }
}

extern "C" void kernel_launch(void* const* d_in, const int* in_sizes, int n_in,
                              void* d_out, int out_size)
{
    const float4* raw4   = (const float4*)d_in[0];
    const float*  z_vals = (const float*)d_in[1];
    const float*  rays_d = (const float*)d_in[2];
    float* out = (float*)d_out;

    const int N = in_sizes[2] / 3;          // num rays from rays_d
    const int warps_per_blk = 8;            // 256 threads
    const int blocks = (N + warps_per_blk - 1) / warps_per_blk;
    nerf_render_kernel<<<blocks, warps_per_blk * 32>>>(raw4, z_vals, rays_d, out, N);
}